// round 7
// baseline (speedup 1.0000x reference)
#include <cuda_runtime.h>

// SymmetricChannel: out[b,l,:] = one_hot(replacement_symbol) if (rand_u < P && argmax(msg)!=0)
//                                else message[b,l,:]
// B=64, L=4096, V=128, P=0.1
//
// rand_u < P is warp-uniform per row -> for ~90% of rows the warp takes a
// pure load->store path with NO reduction (memcpy shape). Only corrupt
// candidates pay the REDUX argmax. Streaming cache hints (no data reuse).

#define NROWS (64 * 4096)
#define VOCAB 128
#define ROWS_PER_WARP 4

__global__ __launch_bounds__(256) void sym_channel_kernel(
    const float* __restrict__ message,
    const float* __restrict__ rand_u,
    const int*   __restrict__ repl_idx,
    float*       __restrict__ out)
{
    const int warp = blockIdx.x * (blockDim.x >> 5) + (threadIdx.x >> 5);
    const int lane = threadIdx.x & 31;
    const int row0 = warp * ROWS_PER_WARP;
    if (row0 >= NROWS) return;

    const float4* __restrict__ min4 = reinterpret_cast<const float4*>(message);
    float4*       __restrict__ out4 = reinterpret_cast<float4*>(out);

    // Per-row scalars: one broadcast vector load each (row0 is 4-aligned)
    const float4 ruv = *reinterpret_cast<const float4*>(rand_u + row0);
    const float ru[ROWS_PER_WARP] = { ruv.x, ruv.y, ruv.z, ruv.w };

    const int base = lane * 4;

    #pragma unroll
    for (int r = 0; r < ROWS_PER_WARP; r++) {
        const size_t off = (size_t)(row0 + r) * (VOCAB / 4) + lane;
        const float4 v = __ldcs(min4 + off);

        // Warp-uniform fast path: not a corruption target -> straight copy,
        // no reduction in the dependency chain.
        if (ru[r] >= 0.1f) {
            __stcs(out4 + off, v);
            continue;
        }

        // Slow path (~10% of rows): need argmax.
        float best = v.x; int bidx = base;
        if (v.y > best) { best = v.y; bidx = base + 1; }
        if (v.z > best) { best = v.z; bidx = base + 2; }
        if (v.w > best) { best = v.w; bidx = base + 3; }

        // Warp argmax: REDUX on bits (uniform [0,1) inputs -> positive floats,
        // bit order == value order); lowest matching lane preserves
        // jnp.argmax first-index tiebreak.
        const unsigned bb   = __float_as_uint(best);
        const unsigned wm   = __reduce_max_sync(0xffffffffu, bb);
        const unsigned ball = __ballot_sync(0xffffffffu, bb == wm);
        const int src  = __ffs(ball) - 1;
        const int amax = __shfl_sync(0xffffffffu, bidx, src);

        float4 o;
        if (amax != 0) {
            // msg != 0 here, so msg_exp == amax.
            const int r1 = __ldg(repl_idx + row0 + r) + 1;
            const int rs = r1 + (r1 >= amax ? 1 : 0);  // in [1, V-1], != amax
            o.x = (rs == base    ) ? 1.0f : 0.0f;
            o.y = (rs == base + 1) ? 1.0f : 0.0f;
            o.z = (rs == base + 2) ? 1.0f : 0.0f;
            o.w = (rs == base + 3) ? 1.0f : 0.0f;
        } else {
            o = v;   // argmax==0 (EOS) -> keep original row
        }
        __stcs(out4 + off, o);
    }
}

extern "C" void kernel_launch(void* const* d_in, const int* in_sizes, int n_in,
                              void* d_out, int out_size)
{
    const float* message  = (const float*)d_in[0];
    const float* rand_u   = (const float*)d_in[1];
    const int*   repl_idx = (const int*)  d_in[2];
    float*       out      = (float*)d_out;

    const int warps_per_block = 8;
    const int rows_per_block  = warps_per_block * ROWS_PER_WARP;       // 32
    const int blocks = (NROWS + rows_per_block - 1) / rows_per_block;  // 8192
    sym_channel_kernel<<<blocks, warps_per_block * 32>>>(message, rand_u, repl_idx, out);
}

// round 8
// speedup vs baseline: 1.0368x; 1.0368x over previous
#include <cuda_runtime.h>

// SymmetricChannel: out[b,l,:] = one_hot(replacement_symbol) if (rand_u < P && argmax(msg)!=0)
//                                else message[b,l,:]
// B=64, L=4096, V=128, P=0.1
//
// 4 rows/warp. Loads pinned front-batched via consecutive asm volatile
// ld.global.v4 (ptxas cannot reorder volatile asm) -> guaranteed MLP=4/thread.
// All compute phase-batched; selection fully branchless (predicated SELs).
// Warp argmax: REDUX.MAX on float bits (uniform [0,1) inputs -> positive
// floats, bit order == value order) + ballot + 1 shfl; lowest matching lane
// preserves jnp.argmax first-index tiebreak.

#define NROWS (64 * 4096)
#define VOCAB 128
#define ROWS_PER_WARP 4

__device__ __forceinline__ float4 ldg_v4_pinned(const float4* p) {
    float4 v;
    asm volatile("ld.global.nc.v4.f32 {%0,%1,%2,%3}, [%4];"
                 : "=f"(v.x), "=f"(v.y), "=f"(v.z), "=f"(v.w)
                 : "l"(p));
    return v;
}

__global__ __launch_bounds__(256) void sym_channel_kernel(
    const float* __restrict__ message,
    const float* __restrict__ rand_u,
    const int*   __restrict__ repl_idx,
    float*       __restrict__ out)
{
    const int warp = blockIdx.x * (blockDim.x >> 5) + (threadIdx.x >> 5);
    const int lane = threadIdx.x & 31;
    const int row0 = warp * ROWS_PER_WARP;
    if (row0 >= NROWS) return;

    const float4* __restrict__ min4 = reinterpret_cast<const float4*>(message);
    float4*       __restrict__ out4 = reinterpret_cast<float4*>(out);

    // ---- Phase 1: all global loads, pinned back-to-back (MLP = 4 + 2) ----
    const size_t off0 = (size_t)row0 * (VOCAB / 4) + lane;
    float4 v0 = ldg_v4_pinned(min4 + off0);
    float4 v1 = ldg_v4_pinned(min4 + off0 + (VOCAB / 4));
    float4 v2 = ldg_v4_pinned(min4 + off0 + 2 * (VOCAB / 4));
    float4 v3 = ldg_v4_pinned(min4 + off0 + 3 * (VOCAB / 4));
    const float4 ruv = *reinterpret_cast<const float4*>(rand_u + row0);
    const int4   riv = *reinterpret_cast<const int4*>(repl_idx + row0);

    float4 v[ROWS_PER_WARP] = { v0, v1, v2, v3 };
    const float ru[ROWS_PER_WARP] = { ruv.x, ruv.y, ruv.z, ruv.w };
    const int   ri[ROWS_PER_WARP] = { riv.x, riv.y, riv.z, riv.w };

    const int base = lane * 4;

    // ---- Phase 2: local argmax for all rows (independent chains) ----
    float best[ROWS_PER_WARP];
    int   bidx[ROWS_PER_WARP];
    #pragma unroll
    for (int r = 0; r < ROWS_PER_WARP; r++) {
        best[r] = v[r].x; bidx[r] = base;
        if (v[r].y > best[r]) { best[r] = v[r].y; bidx[r] = base + 1; }
        if (v[r].z > best[r]) { best[r] = v[r].z; bidx[r] = base + 2; }
        if (v[r].w > best[r]) { best[r] = v[r].w; bidx[r] = base + 3; }
    }

    // ---- Phase 3: warp argmax, REDUX chains batched so latencies overlap ----
    unsigned bb[ROWS_PER_WARP], wm[ROWS_PER_WARP];
    #pragma unroll
    for (int r = 0; r < ROWS_PER_WARP; r++) bb[r] = __float_as_uint(best[r]);
    #pragma unroll
    for (int r = 0; r < ROWS_PER_WARP; r++) wm[r] = __reduce_max_sync(0xffffffffu, bb[r]);
    unsigned ball[ROWS_PER_WARP];
    #pragma unroll
    for (int r = 0; r < ROWS_PER_WARP; r++) ball[r] = __ballot_sync(0xffffffffu, bb[r] == wm[r]);
    int amax[ROWS_PER_WARP];
    #pragma unroll
    for (int r = 0; r < ROWS_PER_WARP; r++)
        amax[r] = __shfl_sync(0xffffffffu, bidx[r], __ffs(ball[r]) - 1);

    // ---- Phase 4: branchless select + store ----
    #pragma unroll
    for (int r = 0; r < ROWS_PER_WARP; r++) {
        const bool combined = (ru[r] < 0.1f) && (amax[r] != 0);
        // msg != 0 when combined, so msg_exp == amax.
        const int r1 = ri[r] + 1;
        const int rs = r1 + (r1 >= amax[r] ? 1 : 0);  // in [1, V-1], != amax
        float4 o;
        o.x = combined ? ((rs == base    ) ? 1.0f : 0.0f) : v[r].x;
        o.y = combined ? ((rs == base + 1) ? 1.0f : 0.0f) : v[r].y;
        o.z = combined ? ((rs == base + 2) ? 1.0f : 0.0f) : v[r].z;
        o.w = combined ? ((rs == base + 3) ? 1.0f : 0.0f) : v[r].w;
        out4[off0 + r * (VOCAB / 4)] = o;
    }
}

extern "C" void kernel_launch(void* const* d_in, const int* in_sizes, int n_in,
                              void* d_out, int out_size)
{
    const float* message  = (const float*)d_in[0];
    const float* rand_u   = (const float*)d_in[1];
    const int*   repl_idx = (const int*)  d_in[2];
    float*       out      = (float*)d_out;

    const int warps_per_block = 8;
    const int rows_per_block  = warps_per_block * ROWS_PER_WARP;       // 32
    const int blocks = (NROWS + rows_per_block - 1) / rows_per_block;  // 8192
    sym_channel_kernel<<<blocks, warps_per_block * 32>>>(message, rand_u, repl_idx, out);
}